// round 5
// baseline (speedup 1.0000x reference)
#include <cuda_runtime.h>
#include <cuda_bf16.h>
#include <math.h>
#include <cstdint>

#define N_NODES 50000
#define N_EDGES 800000
#define NTILES  391          // ceil(50000/128)

// ================= scratch =================
__device__ int   g_is64;
__device__ int   g_src[N_EDGES];
__device__ int   g_dst[N_EDGES];
__device__ int   g_edeg[N_NODES];
__device__ float g_dinv[N_NODES];
__device__ int   g_rowptr[N_NODES + 1];
__device__ int   g_cursor[N_NODES];
__device__ int   g_col[N_EDGES];
__device__ float g_wedge[N_EDGES];

__device__ float g_bufA[N_NODES * 256];   // [h_s1 | h2a] fp32 (feeds agg256)
__device__ float g_h1[N_NODES * 128];
__device__ float g_h2[N_NODES * 128];
__device__ float g_comb[N_NODES * 256];   // [h_struct | h_meta] fp32

// bf16 split operands (plain row-major)
__device__ __nv_bfloat16 g_aggxh[N_NODES * 128];
__device__ __nv_bfloat16 g_aggxl[N_NODES * 128];
__device__ __nv_bfloat16 g_agg2h[N_NODES * 256];
__device__ __nv_bfloat16 g_agg2l[N_NODES * 256];
__device__ __nv_bfloat16 g_combh[N_NODES * 256];
__device__ __nv_bfloat16 g_combl[N_NODES * 256];
// transposed split weights: all six are 16384 elements ([128x128] x5, [64x256] x1)
__device__ __nv_bfloat16 g_wth[6][16384];
__device__ __nv_bfloat16 g_wtl[6][16384];

// ================= helpers =================
__device__ __forceinline__ uint32_t smem_u32(const void* p) {
    uint32_t a;
    asm("{ .reg .u64 t; cvta.to.shared.u64 t, %1; cvt.u32.u64 %0, t; }" : "=r"(a) : "l"(p));
    return a;
}
__device__ __forceinline__ void ldsm_x4(uint32_t* r, uint32_t addr) {
    asm volatile("ldmatrix.sync.aligned.m8n8.x4.shared.b16 {%0,%1,%2,%3}, [%4];"
                 : "=r"(r[0]), "=r"(r[1]), "=r"(r[2]), "=r"(r[3]) : "r"(addr));
}
__device__ __forceinline__ void ldsm_x2(uint32_t* r, uint32_t addr) {
    asm volatile("ldmatrix.sync.aligned.m8n8.x2.shared.b16 {%0,%1}, [%2];"
                 : "=r"(r[0]), "=r"(r[1]) : "r"(addr));
}
__device__ __forceinline__ void mma_bf16(float* d, const uint32_t* a, const uint32_t* b) {
    asm volatile("mma.sync.aligned.m16n8k16.row.col.f32.bf16.bf16.f32 "
                 "{%0,%1,%2,%3}, {%4,%5,%6,%7}, {%8,%9}, {%0,%1,%2,%3};"
                 : "+f"(d[0]), "+f"(d[1]), "+f"(d[2]), "+f"(d[3])
                 : "r"(a[0]), "r"(a[1]), "r"(a[2]), "r"(a[3]), "r"(b[0]), "r"(b[1]));
}
__device__ __forceinline__ void split_bf16(float v, __nv_bfloat16& h, __nv_bfloat16& l) {
    __nv_bfloat16 hb = __float2bfloat16(v);
    h = hb;
    l = __float2bfloat16(v - __bfloat162float(hb));
}

// ================= edge dtype probe + extraction =================
__global__ void k_detect(const int* __restrict__ ei32) {
    __shared__ int nz;
    if (threadIdx.x == 0) nz = 0;
    __syncthreads();
    int local = 0;
    for (int i = threadIdx.x; i < 2048; i += blockDim.x)
        if (ei32[2 * i + 1] != 0) local = 1;
    if (local) atomicOr(&nz, 1);
    __syncthreads();
    if (threadIdx.x == 0) g_is64 = nz ? 0 : 1;
}
__global__ void k_extract(const int* __restrict__ ei32) {
    int e = blockIdx.x * blockDim.x + threadIdx.x;
    if (e < N_EDGES) {
        int s, d;
        if (g_is64) { s = ei32[2 * e]; d = ei32[2 * (N_EDGES + e)]; }
        else        { s = ei32[e];     d = ei32[N_EDGES + e]; }
        g_src[e] = s; g_dst[e] = d;
    }
}

// ================= CSR build =================
__global__ void k_init_deg() {
    int i = blockIdx.x * blockDim.x + threadIdx.x;
    if (i < N_NODES) g_edeg[i] = 0;
}
__global__ void k_count() {
    int e = blockIdx.x * blockDim.x + threadIdx.x;
    if (e < N_EDGES) atomicAdd(&g_edeg[g_dst[e]], 1);
}
__global__ void k_dinv() {
    int i = blockIdx.x * blockDim.x + threadIdx.x;
    if (i < N_NODES) g_dinv[i] = rsqrtf((float)(g_edeg[i] + 1));
}
__global__ void k_scan() {
    __shared__ int part[1024];
    const int t = threadIdx.x;
    const int CH = (N_NODES + 1023) / 1024;
    int start = t * CH;
    int s = 0;
    for (int i = 0; i < CH; i++) { int idx = start + i; if (idx < N_NODES) s += g_edeg[idx]; }
    part[t] = s;
    __syncthreads();
    for (int off = 1; off < 1024; off <<= 1) {
        int v = (t >= off) ? part[t - off] : 0;
        __syncthreads();
        part[t] += v;
        __syncthreads();
    }
    int run = (t == 0) ? 0 : part[t - 1];
    for (int i = 0; i < CH; i++) {
        int idx = start + i;
        if (idx < N_NODES) { g_rowptr[idx] = run; g_cursor[idx] = run; run += g_edeg[idx]; }
    }
    if (t == 1023) g_rowptr[N_NODES] = run;
}
__global__ void k_fill() {
    int e = blockIdx.x * blockDim.x + threadIdx.x;
    if (e < N_EDGES) {
        int s = g_src[e], d = g_dst[e];
        int p = atomicAdd(&g_cursor[d], 1);
        g_col[p] = s;
        g_wedge[p] = g_dinv[s] * g_dinv[d];
    }
}

// ================= aggregation (emit bf16 hi/lo) =================
__global__ void k_agg128(const float* __restrict__ in,
                         __nv_bfloat16* __restrict__ oh, __nv_bfloat16* __restrict__ ol) {
    int n = blockIdx.x, c = threadIdx.x;  // 128 threads
    float dn = g_dinv[n];
    float acc = dn * dn * in[n * 128 + c];
    int j = g_rowptr[n], end = g_rowptr[n + 1];
    for (; j + 1 < end; j += 2) {
        int s0 = g_col[j], s1 = g_col[j + 1];
        float w0 = g_wedge[j], w1 = g_wedge[j + 1];
        acc += w0 * in[s0 * 128 + c];
        acc += w1 * in[s1 * 128 + c];
    }
    if (j < end) acc += g_wedge[j] * in[g_col[j] * 128 + c];
    split_bf16(acc, oh[n * 128 + c], ol[n * 128 + c]);
}
__global__ void k_agg256(const float* __restrict__ in,
                         __nv_bfloat16* __restrict__ oh, __nv_bfloat16* __restrict__ ol) {
    int n = blockIdx.x, c = threadIdx.x;  // 256 threads
    float dn = g_dinv[n];
    float acc = dn * dn * in[n * 256 + c];
    int j = g_rowptr[n], end = g_rowptr[n + 1];
    for (; j + 1 < end; j += 2) {
        int s0 = g_col[j], s1 = g_col[j + 1];
        float w0 = g_wedge[j], w1 = g_wedge[j + 1];
        acc += w0 * in[s0 * 256 + c];
        acc += w1 * in[s1 * 256 + c];
    }
    if (j < end) acc += g_wedge[j] * in[g_col[j] * 256 + c];
    split_bf16(acc, oh[n * 256 + c], ol[n * 256 + c]);
}
__global__ void k_convC(const float* __restrict__ comb,
                        __nv_bfloat16* __restrict__ oh, __nv_bfloat16* __restrict__ ol) {
    int i = blockIdx.x * blockDim.x + threadIdx.x;  // over N*256
    float v = comb[i];
    split_bf16(v, oh[i], ol[i]);
}

// weights -> transposed split: Wt[n][k] from W[k][n]
struct PrepB { const float* W[6]; int K[6]; int N[6]; };
__global__ void k_prepB(PrepB p) {
    int b = blockIdx.x;
    const float* W = p.W[b];
    int K = p.K[b], N = p.N[b];
    for (int idx = threadIdx.x; idx < K * N; idx += blockDim.x) {
        int k = idx / N, n = idx % N;
        split_bf16(W[idx], g_wth[b][n * K + k], g_wtl[b][n * K + k]);
    }
}

// ================= split-bf16 mma.sync GEMM =================
struct MJobs {
    const __nv_bfloat16* Ah[3];
    const __nv_bfloat16* Al[3];
    const __nv_bfloat16* Bh[3];
    const __nv_bfloat16* Bl[3];
    const float*         bias[3];
    float*               C[3];
    int                  lda[3];
    int                  ldc[3];
};

// C[128 x NN] tile per CTA; full K in smem. 256 thr = 8 warps (2m x 4n), warp tile 64 x NN/4.
template <int NN, int KK>
__global__ __launch_bounds__(256, 1) void k_mma(MJobs jobs, int do_relu) {
    extern __shared__ __align__(16) unsigned char smem[];
    constexpr int NCH = KK / 8;          // 16B chunks per row
    constexpr int AB  = 128 * KK * 2;    // bytes of one A split
    constexpr int BB  = NN * KK * 2;     // bytes of one B split
    constexpr int NI  = NN / 32;         // n8 tiles per warp (4 or 2)
    constexpr int KSTEPS = KK / 16;

    const int job = blockIdx.z;
    const int bm  = blockIdx.y * 128;
    const int tid = threadIdx.x;
    const int lane = tid & 31, warp = tid >> 5;
    const int wm = (warp >> 2) * 64;
    const int wn = (warp & 3) * (NN / 4);

    const __nv_bfloat16* Ah = jobs.Ah[job];
    const __nv_bfloat16* Al = jobs.Al[job];
    const int lda = jobs.lda[job];

    // ---- load tiles to smem (XOR-swizzled 16B chunks) ----
    {
        const int ldach = lda / 8;
        uint4* s = reinterpret_cast<uint4*>(smem);
        for (int idx = tid; idx < 128 * NCH; idx += 256) {
            int r = idx / NCH, cc = idx % NCH;
            long gr = bm + r; if (gr >= N_NODES) gr = N_NODES - 1;
            int sp = r * NCH + (cc ^ (r & 7));
            s[sp]                = reinterpret_cast<const uint4*>(Ah)[gr * ldach + cc];
            s[sp + AB / 16]      = reinterpret_cast<const uint4*>(Al)[gr * ldach + cc];
        }
        const uint4* bh = reinterpret_cast<const uint4*>(jobs.Bh[job]);
        const uint4* bl = reinterpret_cast<const uint4*>(jobs.Bl[job]);
        uint4* sb = reinterpret_cast<uint4*>(smem + 2 * AB);
        for (int idx = tid; idx < NN * NCH; idx += 256) {
            int r = idx / NCH, cc = idx % NCH;
            int sp = r * NCH + (cc ^ (r & 7));
            sb[sp]           = bh[idx];
            sb[sp + BB / 16] = bl[idx];
        }
    }
    __syncthreads();

    const uint32_t sbase = smem_u32(smem);

    // ---- per-thread fragment address bases ----
    const int group = lane >> 3, within = lane & 7;
    const int kaddA = group >> 1;
    uint32_t abyte[4]; int rx[4];
    {
        int mrow = wm + (group & 1) * 8 + within;
#pragma unroll
        for (int mi = 0; mi < 4; mi++) {
            int r = mrow + mi * 16;
            abyte[mi] = (uint32_t)(r * NCH) << 4;
            rx[mi] = r & 7;
        }
    }
    const int laneB = lane & 15;
    const int kaddB = laneB >> 3, withinB = laneB & 7;
    uint32_t bbyte[NI]; int nx[NI];
#pragma unroll
    for (int ni = 0; ni < NI; ni++) {
        int r = wn + ni * 8 + withinB;
        bbyte[ni] = (uint32_t)(r * NCH) << 4;
        nx[ni] = r & 7;
    }

    float acc[4][NI][4];
#pragma unroll
    for (int mi = 0; mi < 4; mi++)
#pragma unroll
        for (int ni = 0; ni < NI; ni++)
#pragma unroll
            for (int q = 0; q < 4; q++) acc[mi][ni][q] = 0.0f;

    // ---- 3-term split product: (Ahi,Bhi), (Ahi,Blo), (Alo,Bhi) ----
#pragma unroll 1
    for (int pass = 0; pass < 3; pass++) {
        const uint32_t aoff = sbase + (pass == 2 ? AB : 0);
        const uint32_t boff = sbase + 2 * AB + (pass == 1 ? BB : 0);
#pragma unroll
        for (int s = 0; s < KSTEPS; s++) {
            const int kc = s * 2;
            uint32_t bf[NI][2];
#pragma unroll
            for (int ni = 0; ni < NI; ni++)
                ldsm_x2(bf[ni], boff + bbyte[ni] + ((uint32_t)((kc + kaddB) ^ nx[ni]) << 4));
#pragma unroll
            for (int mi = 0; mi < 4; mi++) {
                uint32_t af[4];
                ldsm_x4(af, aoff + abyte[mi] + ((uint32_t)((kc + kaddA) ^ rx[mi]) << 4));
#pragma unroll
                for (int ni = 0; ni < NI; ni++)
                    mma_bf16(acc[mi][ni], af, bf[ni]);
            }
        }
    }

    // ---- epilogue ----
    const float* bias = jobs.bias[job];
    float* C = jobs.C[job];
    const int ldc = jobs.ldc[job];
    const int g = lane >> 2, tc = lane & 3;
#pragma unroll
    for (int mi = 0; mi < 4; mi++) {
#pragma unroll
        for (int ni = 0; ni < NI; ni++) {
            int n0 = wn + ni * 8 + tc * 2;
            float b0 = bias[n0], b1 = bias[n0 + 1];
            int m0 = bm + wm + mi * 16 + g;
            float v0 = acc[mi][ni][0] + b0, v1 = acc[mi][ni][1] + b1;
            float v2 = acc[mi][ni][2] + b0, v3 = acc[mi][ni][3] + b1;
            if (do_relu) {
                v0 = fmaxf(v0, 0.0f); v1 = fmaxf(v1, 0.0f);
                v2 = fmaxf(v2, 0.0f); v3 = fmaxf(v3, 0.0f);
            }
            if (m0 < N_NODES)
                *reinterpret_cast<float2*>(C + (size_t)m0 * ldc + n0) = make_float2(v0, v1);
            if (m0 + 8 < N_NODES)
                *reinterpret_cast<float2*>(C + (size_t)(m0 + 8) * ldc + n0) = make_float2(v2, v3);
        }
    }
}

// ================= attention fusion =================
__global__ void k_attn(const float* __restrict__ watt, const float* __restrict__ batt) {
    int n = blockIdx.x;
    int c = threadIdx.x;  // 128
    float h1v = g_h1[n * 128 + c];
    float h2v = g_h2[n * 128 + c];
    float wa = watt[c];
    float p1 = h1v * wa;
    float p2 = h2v * wa;
#pragma unroll
    for (int o = 16; o > 0; o >>= 1) {
        p1 += __shfl_down_sync(0xFFFFFFFFu, p1, o);
        p2 += __shfl_down_sync(0xFFFFFFFFu, p2, o);
    }
    __shared__ float s1[4], s2[4];
    __shared__ float a1s;
    int w = c >> 5;
    if ((c & 31) == 0) { s1[w] = p1; s2[w] = p2; }
    __syncthreads();
    if (c == 0) {
        float S1 = s1[0] + s1[1] + s1[2] + s1[3] + batt[0];
        float S2 = s2[0] + s2[1] + s2[2] + s2[3] + batt[0];
        a1s = 1.0f / (1.0f + expf(S2 - S1));
    }
    __syncthreads();
    float a1 = a1s;
    g_comb[n * 256 + 128 + c] = a1 * h1v + (1.0f - a1) * h2v;
}

// ================= launch =================
extern "C" void kernel_launch(void* const* d_in, const int* in_sizes, int n_in,
                              void* d_out, int out_size) {
    const float* x    = (const float*)d_in[0];
    const int*   ei32 = (const int*)d_in[1];
    const float* W_s1 = (const float*)d_in[2];
    const float* b_s1 = (const float*)d_in[3];
    const float* W_s2 = (const float*)d_in[4];
    const float* b_s2 = (const float*)d_in[5];
    const float* W_m1 = (const float*)d_in[6];
    const float* b_m1 = (const float*)d_in[7];
    const float* W_m21 = (const float*)d_in[8];
    const float* b_m21 = (const float*)d_in[9];
    const float* W_m22 = (const float*)d_in[10];
    const float* b_m22 = (const float*)d_in[11];
    const float* W_att = (const float*)d_in[12];
    const float* b_att = (const float*)d_in[13];
    const float* W_fc  = (const float*)d_in[14];
    const float* b_fc  = (const float*)d_in[15];
    float* out = (float*)d_out;

    float* bufA; cudaGetSymbolAddress((void**)&bufA, g_bufA);
    float* h1;   cudaGetSymbolAddress((void**)&h1, g_h1);
    float* h2;   cudaGetSymbolAddress((void**)&h2, g_h2);
    float* comb; cudaGetSymbolAddress((void**)&comb, g_comb);
    __nv_bfloat16 *aggxh, *aggxl, *agg2h, *agg2l, *combh, *combl, *wth, *wtl;
    cudaGetSymbolAddress((void**)&aggxh, g_aggxh);
    cudaGetSymbolAddress((void**)&aggxl, g_aggxl);
    cudaGetSymbolAddress((void**)&agg2h, g_agg2h);
    cudaGetSymbolAddress((void**)&agg2l, g_agg2l);
    cudaGetSymbolAddress((void**)&combh, g_combh);
    cudaGetSymbolAddress((void**)&combl, g_combl);
    cudaGetSymbolAddress((void**)&wth, g_wth);
    cudaGetSymbolAddress((void**)&wtl, g_wtl);

    const int SM128 = 2 * (128 * 128 * 2) + 2 * (128 * 128 * 2);  // 131072
    const int SM64  = 2 * (128 * 256 * 2) + 2 * (64 * 256 * 2);   // 196608
    static bool attr_done = false;
    if (!attr_done) {
        cudaFuncSetAttribute(k_mma<128, 128>, cudaFuncAttributeMaxDynamicSharedMemorySize, SM128);
        cudaFuncSetAttribute(k_mma<64, 256>,  cudaFuncAttributeMaxDynamicSharedMemorySize, SM64);
        attr_done = true;
    }

    const int TB = 256;
    k_detect<<<1, 256>>>(ei32);
    k_extract<<<(N_EDGES + TB - 1) / TB, TB>>>(ei32);

    k_init_deg<<<(N_NODES + TB - 1) / TB, TB>>>();
    k_count<<<(N_EDGES + TB - 1) / TB, TB>>>();
    k_dinv<<<(N_NODES + TB - 1) / TB, TB>>>();
    k_scan<<<1, 1024>>>();
    k_fill<<<(N_EDGES + TB - 1) / TB, TB>>>();

    // weight prep
    {
        PrepB p;
        p.W[0] = W_s1;  p.K[0] = 128; p.N[0] = 128;
        p.W[1] = W_m21; p.K[1] = 128; p.N[1] = 128;
        p.W[2] = W_m1;  p.K[2] = 128; p.N[2] = 128;
        p.W[3] = W_s2;  p.K[3] = 128; p.N[3] = 128;
        p.W[4] = W_m22; p.K[4] = 128; p.N[4] = 128;
        p.W[5] = W_fc;  p.K[5] = 256; p.N[5] = 64;
        k_prepB<<<6, 256>>>(p);
    }

    // agg_x (bf16 split)
    k_agg128<<<N_NODES, 128>>>(x, aggxh, aggxl);

    // layer-1: 3 GEMMs off shared aggregation
    {
        MJobs j;
        for (int q = 0; q < 3; q++) { j.Ah[q] = aggxh; j.Al[q] = aggxl; j.lda[q] = 128; }
        j.Bh[0] = wth + 0 * 16384; j.Bl[0] = wtl + 0 * 16384; j.bias[0] = b_s1;  j.C[0] = bufA;       j.ldc[0] = 256;
        j.Bh[1] = wth + 1 * 16384; j.Bl[1] = wtl + 1 * 16384; j.bias[1] = b_m21; j.C[1] = bufA + 128; j.ldc[1] = 256;
        j.Bh[2] = wth + 2 * 16384; j.Bl[2] = wtl + 2 * 16384; j.bias[2] = b_m1;  j.C[2] = h1;         j.ldc[2] = 128;
        k_mma<128, 128><<<dim3(1, NTILES, 3), 256, SM128>>>(j, 1);
    }

    // layer-2 shared aggregation (bf16 split, 256 ch)
    k_agg256<<<N_NODES, 256>>>(bufA, agg2h, agg2l);

    // layer-2: 2 GEMMs
    {
        MJobs j;
        j.Ah[0] = agg2h;       j.Al[0] = agg2l;       j.lda[0] = 256;
        j.Ah[1] = agg2h + 128; j.Al[1] = agg2l + 128; j.lda[1] = 256;
        j.Ah[2] = j.Ah[0];     j.Al[2] = j.Al[0];     j.lda[2] = 256;
        j.Bh[0] = wth + 3 * 16384; j.Bl[0] = wtl + 3 * 16384; j.bias[0] = b_s2;  j.C[0] = comb; j.ldc[0] = 256;
        j.Bh[1] = wth + 4 * 16384; j.Bl[1] = wtl + 4 * 16384; j.bias[1] = b_m22; j.C[1] = h2;   j.ldc[1] = 128;
        j.Bh[2] = j.Bh[0]; j.Bl[2] = j.Bl[0]; j.bias[2] = j.bias[0]; j.C[2] = j.C[0]; j.ldc[2] = j.ldc[0];
        k_mma<128, 128><<<dim3(1, NTILES, 2), 256, SM128>>>(j, 1);
    }

    // attention fusion -> comb[:, 128:]
    k_attn<<<N_NODES, 128>>>(W_att, b_att);

    // comb -> bf16 split, then FC
    k_convC<<<(N_NODES * 256) / 256, 256>>>(comb, combh, combl);
    {
        MJobs j;
        for (int q = 0; q < 3; q++) {
            j.Ah[q] = combh; j.Al[q] = combl; j.lda[q] = 256;
            j.Bh[q] = wth + 5 * 16384; j.Bl[q] = wtl + 5 * 16384;
            j.bias[q] = b_fc; j.C[q] = out; j.ldc[q] = 64;
        }
        k_mma<64, 256><<<dim3(1, NTILES, 1), 256, SM64>>>(j, 0);
    }

    (void)in_sizes; (void)n_in; (void)out_size;
}

// round 6
// speedup vs baseline: 1.0024x; 1.0024x over previous
#include <cuda_runtime.h>
#include <cuda_bf16.h>
#include <math.h>
#include <cstdint>

#define N_NODES 50000
#define N_EDGES 800000
#define NTILES  391          // ceil(50000/128)

// ================= scratch =================
__device__ int   g_is64;
__device__ int   g_src[N_EDGES];
__device__ int   g_dst[N_EDGES];
__device__ int   g_edeg[N_NODES];
__device__ float g_dinv[N_NODES];
__device__ int   g_rowptr[N_NODES + 1];
__device__ int   g_cursor[N_NODES];
__device__ int   g_col[N_EDGES];
__device__ float g_wedge[N_EDGES];

__device__ float g_bufA[N_NODES * 256];   // [h_s1 | h2a] fp32 (feeds agg256)
__device__ float g_h1[N_NODES * 128];
__device__ float g_h2[N_NODES * 128];

// bf16 split operands (plain row-major)
__device__ __nv_bfloat16 g_aggxh[N_NODES * 128];
__device__ __nv_bfloat16 g_aggxl[N_NODES * 128];
__device__ __nv_bfloat16 g_agg2h[N_NODES * 256];
__device__ __nv_bfloat16 g_agg2l[N_NODES * 256];
__device__ __nv_bfloat16 g_combh[N_NODES * 256];  // [h_struct | h_meta] split
__device__ __nv_bfloat16 g_combl[N_NODES * 256];
__device__ __nv_bfloat16 g_wth[6][16384];
__device__ __nv_bfloat16 g_wtl[6][16384];

// ================= helpers =================
__device__ __forceinline__ uint32_t smem_u32(const void* p) {
    uint32_t a;
    asm("{ .reg .u64 t; cvta.to.shared.u64 t, %1; cvt.u32.u64 %0, t; }" : "=r"(a) : "l"(p));
    return a;
}
__device__ __forceinline__ void ldsm_x4(uint32_t* r, uint32_t addr) {
    asm volatile("ldmatrix.sync.aligned.m8n8.x4.shared.b16 {%0,%1,%2,%3}, [%4];"
                 : "=r"(r[0]), "=r"(r[1]), "=r"(r[2]), "=r"(r[3]) : "r"(addr));
}
__device__ __forceinline__ void ldsm_x2(uint32_t* r, uint32_t addr) {
    asm volatile("ldmatrix.sync.aligned.m8n8.x2.shared.b16 {%0,%1}, [%2];"
                 : "=r"(r[0]), "=r"(r[1]) : "r"(addr));
}
__device__ __forceinline__ void mma_bf16(float* d, const uint32_t* a, const uint32_t* b) {
    asm volatile("mma.sync.aligned.m16n8k16.row.col.f32.bf16.bf16.f32 "
                 "{%0,%1,%2,%3}, {%4,%5,%6,%7}, {%8,%9}, {%0,%1,%2,%3};"
                 : "+f"(d[0]), "+f"(d[1]), "+f"(d[2]), "+f"(d[3])
                 : "r"(a[0]), "r"(a[1]), "r"(a[2]), "r"(a[3]), "r"(b[0]), "r"(b[1]));
}
__device__ __forceinline__ void split_bf16(float v, __nv_bfloat16& h, __nv_bfloat16& l) {
    __nv_bfloat16 hb = __float2bfloat16(v);
    h = hb;
    l = __float2bfloat16(v - __bfloat162float(hb));
}

// ================= fused detect + edeg zero =================
__global__ void k_detect_init(const int* __restrict__ ei32) {
    int i = blockIdx.x * blockDim.x + threadIdx.x;
    if (i < N_NODES) g_edeg[i] = 0;
    if (blockIdx.x == 0) {
        __shared__ int nz;
        if (threadIdx.x == 0) nz = 0;
        __syncthreads();
        int local = 0;
        for (int q = threadIdx.x; q < 2048; q += blockDim.x)
            if (ei32[2 * q + 1] != 0) local = 1;
        if (local) atomicOr(&nz, 1);
        __syncthreads();
        if (threadIdx.x == 0) g_is64 = nz ? 0 : 1;
    }
}

// ================= fused extract + count =================
__global__ void k_extract_count(const int* __restrict__ ei32) {
    int e = blockIdx.x * blockDim.x + threadIdx.x;
    if (e < N_EDGES) {
        int s, d;
        if (g_is64) { s = ei32[2 * e]; d = ei32[2 * (N_EDGES + e)]; }
        else        { s = ei32[e];     d = ei32[N_EDGES + e]; }
        g_src[e] = s; g_dst[e] = d;
        atomicAdd(&g_edeg[d], 1);
    }
}

// ================= fused scan + dinv =================
__global__ void k_scan_dinv() {
    __shared__ int part[1024];
    const int t = threadIdx.x;
    const int CH = (N_NODES + 1023) / 1024;
    int start = t * CH;
    int s = 0;
    for (int i = 0; i < CH; i++) { int idx = start + i; if (idx < N_NODES) s += g_edeg[idx]; }
    part[t] = s;
    __syncthreads();
    for (int off = 1; off < 1024; off <<= 1) {
        int v = (t >= off) ? part[t - off] : 0;
        __syncthreads();
        part[t] += v;
        __syncthreads();
    }
    int run = (t == 0) ? 0 : part[t - 1];
    for (int i = 0; i < CH; i++) {
        int idx = start + i;
        if (idx < N_NODES) {
            g_rowptr[idx] = run;
            g_cursor[idx] = run;
            g_dinv[idx] = rsqrtf((float)(g_edeg[idx] + 1));
            run += g_edeg[idx];
        }
    }
    if (t == 1023) g_rowptr[N_NODES] = run;
}

__global__ void k_fill() {
    int e = blockIdx.x * blockDim.x + threadIdx.x;
    if (e < N_EDGES) {
        int s = g_src[e], d = g_dst[e];
        int p = atomicAdd(&g_cursor[d], 1);
        g_col[p] = s;
        g_wedge[p] = g_dinv[s] * g_dinv[d];
    }
}

// weights -> transposed split: Wt[n][k] from W[k][n]
struct PrepB { const float* W[6]; int K[6]; int N[6]; };
__global__ void k_prepB(PrepB p) {
    int b = blockIdx.x;
    const float* W = p.W[b];
    int K = p.K[b], N = p.N[b];
    for (int idx = threadIdx.x; idx < K * N; idx += blockDim.x) {
        int k = idx / N, n = idx % N;
        split_bf16(W[idx], g_wth[b][n * K + k], g_wtl[b][n * K + k]);
    }
}

// ================= aggregation with smem edge staging =================
__global__ void k_agg128(const float* __restrict__ in,
                         __nv_bfloat16* __restrict__ oh, __nv_bfloat16* __restrict__ ol) {
    __shared__ int   scol[128];
    __shared__ float swt[128];
    const int n = blockIdx.x, c = threadIdx.x;  // 128 threads
    float dn = g_dinv[n];
    float acc = dn * dn * in[n * 128 + c];
    const int beg = g_rowptr[n], end = g_rowptr[n + 1];
    for (int base = beg; base < end; base += 128) {
        int cnt = end - base; if (cnt > 128) cnt = 128;
        __syncthreads();
        if (c < cnt) { scol[c] = g_col[base + c]; swt[c] = g_wedge[base + c]; }
        __syncthreads();
        int j = 0;
        for (; j + 3 < cnt; j += 4) {
            int   i0 = scol[j],   i1 = scol[j+1], i2 = scol[j+2], i3 = scol[j+3];
            float w0 = swt[j],    w1 = swt[j+1],  w2 = swt[j+2],  w3 = swt[j+3];
            float v0 = in[i0 * 128 + c], v1 = in[i1 * 128 + c];
            float v2 = in[i2 * 128 + c], v3 = in[i3 * 128 + c];
            acc += w0 * v0; acc += w1 * v1; acc += w2 * v2; acc += w3 * v3;
        }
        for (; j < cnt; j++) acc += swt[j] * in[scol[j] * 128 + c];
    }
    split_bf16(acc, oh[n * 128 + c], ol[n * 128 + c]);
}

__global__ void k_agg256(const float* __restrict__ in,
                         __nv_bfloat16* __restrict__ oh, __nv_bfloat16* __restrict__ ol) {
    __shared__ int   scol[128];
    __shared__ float swt[128];
    const int n = blockIdx.x, c = threadIdx.x;  // 256 threads
    float dn = g_dinv[n];
    float acc = dn * dn * in[n * 256 + c];
    const int beg = g_rowptr[n], end = g_rowptr[n + 1];
    for (int base = beg; base < end; base += 128) {
        int cnt = end - base; if (cnt > 128) cnt = 128;
        __syncthreads();
        if (c < cnt) { scol[c] = g_col[base + c]; swt[c] = g_wedge[base + c]; }
        __syncthreads();
        int j = 0;
        for (; j + 3 < cnt; j += 4) {
            int   i0 = scol[j],   i1 = scol[j+1], i2 = scol[j+2], i3 = scol[j+3];
            float w0 = swt[j],    w1 = swt[j+1],  w2 = swt[j+2],  w3 = swt[j+3];
            float v0 = in[i0 * 256 + c], v1 = in[i1 * 256 + c];
            float v2 = in[i2 * 256 + c], v3 = in[i3 * 256 + c];
            acc += w0 * v0; acc += w1 * v1; acc += w2 * v2; acc += w3 * v3;
        }
        for (; j < cnt; j++) acc += swt[j] * in[scol[j] * 256 + c];
    }
    split_bf16(acc, oh[n * 256 + c], ol[n * 256 + c]);
}

// ================= split-bf16 mma.sync GEMM =================
struct MJobs {
    const __nv_bfloat16* Ah[3];
    const __nv_bfloat16* Al[3];
    const __nv_bfloat16* Bh[3];
    const __nv_bfloat16* Bl[3];
    const float*         bias[3];
    float*               C[3];
    __nv_bfloat16*       Cbh[3];
    __nv_bfloat16*       Cbl[3];
    int                  lda[3];
    int                  ldc[3];
    int                  split[3];   // 1 => write split bf16 to Cbh/Cbl instead of fp32 C
};

template <int NN, int KK>
__global__ __launch_bounds__(256, 1) void k_mma(MJobs jobs, int do_relu) {
    extern __shared__ __align__(16) unsigned char smem[];
    constexpr int NCH = KK / 8;
    constexpr int AB  = 128 * KK * 2;
    constexpr int BB  = NN * KK * 2;
    constexpr int NI  = NN / 32;
    constexpr int KSTEPS = KK / 16;

    const int job = blockIdx.z;
    const int bm  = blockIdx.y * 128;
    const int tid = threadIdx.x;
    const int lane = tid & 31, warp = tid >> 5;
    const int wm = (warp >> 2) * 64;
    const int wn = (warp & 3) * (NN / 4);

    const __nv_bfloat16* Ah = jobs.Ah[job];
    const __nv_bfloat16* Al = jobs.Al[job];
    const int lda = jobs.lda[job];

    {
        const int ldach = lda / 8;
        uint4* s = reinterpret_cast<uint4*>(smem);
        for (int idx = tid; idx < 128 * NCH; idx += 256) {
            int r = idx / NCH, cc = idx % NCH;
            long gr = bm + r; if (gr >= N_NODES) gr = N_NODES - 1;
            int sp = r * NCH + (cc ^ (r & 7));
            s[sp]           = reinterpret_cast<const uint4*>(Ah)[gr * ldach + cc];
            s[sp + AB / 16] = reinterpret_cast<const uint4*>(Al)[gr * ldach + cc];
        }
        const uint4* bh = reinterpret_cast<const uint4*>(jobs.Bh[job]);
        const uint4* bl = reinterpret_cast<const uint4*>(jobs.Bl[job]);
        uint4* sb = reinterpret_cast<uint4*>(smem + 2 * AB);
        for (int idx = tid; idx < NN * NCH; idx += 256) {
            int r = idx / NCH, cc = idx % NCH;
            int sp = r * NCH + (cc ^ (r & 7));
            sb[sp]           = bh[idx];
            sb[sp + BB / 16] = bl[idx];
        }
    }
    __syncthreads();

    const uint32_t sbase = smem_u32(smem);
    const int group = lane >> 3, within = lane & 7;
    const int kaddA = group >> 1;
    uint32_t abyte[4]; int rx[4];
    {
        int mrow = wm + (group & 1) * 8 + within;
#pragma unroll
        for (int mi = 0; mi < 4; mi++) {
            int r = mrow + mi * 16;
            abyte[mi] = (uint32_t)(r * NCH) << 4;
            rx[mi] = r & 7;
        }
    }
    const int laneB = lane & 15;
    const int kaddB = laneB >> 3, withinB = laneB & 7;
    uint32_t bbyte[NI]; int nx[NI];
#pragma unroll
    for (int ni = 0; ni < NI; ni++) {
        int r = wn + ni * 8 + withinB;
        bbyte[ni] = (uint32_t)(r * NCH) << 4;
        nx[ni] = r & 7;
    }

    float acc[4][NI][4];
#pragma unroll
    for (int mi = 0; mi < 4; mi++)
#pragma unroll
        for (int ni = 0; ni < NI; ni++)
#pragma unroll
            for (int q = 0; q < 4; q++) acc[mi][ni][q] = 0.0f;

#pragma unroll 1
    for (int pass = 0; pass < 3; pass++) {
        const uint32_t aoff = sbase + (pass == 2 ? AB : 0);
        const uint32_t boff = sbase + 2 * AB + (pass == 1 ? BB : 0);
#pragma unroll
        for (int s = 0; s < KSTEPS; s++) {
            const int kc = s * 2;
            uint32_t bf[NI][2];
#pragma unroll
            for (int ni = 0; ni < NI; ni++)
                ldsm_x2(bf[ni], boff + bbyte[ni] + ((uint32_t)((kc + kaddB) ^ nx[ni]) << 4));
#pragma unroll
            for (int mi = 0; mi < 4; mi++) {
                uint32_t af[4];
                ldsm_x4(af, aoff + abyte[mi] + ((uint32_t)((kc + kaddA) ^ rx[mi]) << 4));
#pragma unroll
                for (int ni = 0; ni < NI; ni++)
                    mma_bf16(acc[mi][ni], af, bf[ni]);
            }
        }
    }

    const float* bias = jobs.bias[job];
    float* C = jobs.C[job];
    __nv_bfloat16* Cbh = jobs.Cbh[job];
    __nv_bfloat16* Cbl = jobs.Cbl[job];
    const int ldc = jobs.ldc[job];
    const int splt = jobs.split[job];
    const int g = lane >> 2, tc = lane & 3;
#pragma unroll
    for (int mi = 0; mi < 4; mi++) {
#pragma unroll
        for (int ni = 0; ni < NI; ni++) {
            int n0 = wn + ni * 8 + tc * 2;
            float b0 = bias[n0], b1 = bias[n0 + 1];
            int m0 = bm + wm + mi * 16 + g;
            float v0 = acc[mi][ni][0] + b0, v1 = acc[mi][ni][1] + b1;
            float v2 = acc[mi][ni][2] + b0, v3 = acc[mi][ni][3] + b1;
            if (do_relu) {
                v0 = fmaxf(v0, 0.0f); v1 = fmaxf(v1, 0.0f);
                v2 = fmaxf(v2, 0.0f); v3 = fmaxf(v3, 0.0f);
            }
            if (splt) {
                __nv_bfloat16 h0, l0, h1b, l1;
                if (m0 < N_NODES) {
                    split_bf16(v0, h0, l0); split_bf16(v1, h1b, l1);
                    *reinterpret_cast<__nv_bfloat162*>(Cbh + (size_t)m0 * ldc + n0) = __nv_bfloat162{h0, h1b};
                    *reinterpret_cast<__nv_bfloat162*>(Cbl + (size_t)m0 * ldc + n0) = __nv_bfloat162{l0, l1};
                }
                if (m0 + 8 < N_NODES) {
                    split_bf16(v2, h0, l0); split_bf16(v3, h1b, l1);
                    *reinterpret_cast<__nv_bfloat162*>(Cbh + (size_t)(m0 + 8) * ldc + n0) = __nv_bfloat162{h0, h1b};
                    *reinterpret_cast<__nv_bfloat162*>(Cbl + (size_t)(m0 + 8) * ldc + n0) = __nv_bfloat162{l0, l1};
                }
            } else {
                if (m0 < N_NODES)
                    *reinterpret_cast<float2*>(C + (size_t)m0 * ldc + n0) = make_float2(v0, v1);
                if (m0 + 8 < N_NODES)
                    *reinterpret_cast<float2*>(C + (size_t)(m0 + 8) * ldc + n0) = make_float2(v2, v3);
            }
        }
    }
}

// ================= attention fusion (2 nodes/block, writes split bf16 meta) =================
__global__ void k_attn(const float* __restrict__ watt, const float* __restrict__ batt) {
    const int half = threadIdx.x >> 7;          // 0/1
    const int c = threadIdx.x & 127;
    const int n = blockIdx.x * 2 + half;
    float h1v = g_h1[n * 128 + c];
    float h2v = g_h2[n * 128 + c];
    float wa = watt[c];
    float p1 = h1v * wa;
    float p2 = h2v * wa;
#pragma unroll
    for (int o = 16; o > 0; o >>= 1) {
        p1 += __shfl_down_sync(0xFFFFFFFFu, p1, o);
        p2 += __shfl_down_sync(0xFFFFFFFFu, p2, o);
    }
    __shared__ float s1[8], s2[8];
    __shared__ float a1s[2];
    int w = threadIdx.x >> 5;   // 0..7
    if ((threadIdx.x & 31) == 0) { s1[w] = p1; s2[w] = p2; }
    __syncthreads();
    if (c == 0) {
        int b = half * 4;
        float S1 = s1[b] + s1[b+1] + s1[b+2] + s1[b+3] + batt[0];
        float S2 = s2[b] + s2[b+1] + s2[b+2] + s2[b+3] + batt[0];
        a1s[half] = 1.0f / (1.0f + expf(S2 - S1));
    }
    __syncthreads();
    float a1 = a1s[half];
    float v = a1 * h1v + (1.0f - a1) * h2v;
    __nv_bfloat16 h, l;
    split_bf16(v, h, l);
    g_combh[n * 256 + 128 + c] = h;
    g_combl[n * 256 + 128 + c] = l;
}

// ================= launch =================
extern "C" void kernel_launch(void* const* d_in, const int* in_sizes, int n_in,
                              void* d_out, int out_size) {
    const float* x    = (const float*)d_in[0];
    const int*   ei32 = (const int*)d_in[1];
    const float* W_s1 = (const float*)d_in[2];
    const float* b_s1 = (const float*)d_in[3];
    const float* W_s2 = (const float*)d_in[4];
    const float* b_s2 = (const float*)d_in[5];
    const float* W_m1 = (const float*)d_in[6];
    const float* b_m1 = (const float*)d_in[7];
    const float* W_m21 = (const float*)d_in[8];
    const float* b_m21 = (const float*)d_in[9];
    const float* W_m22 = (const float*)d_in[10];
    const float* b_m22 = (const float*)d_in[11];
    const float* W_att = (const float*)d_in[12];
    const float* b_att = (const float*)d_in[13];
    const float* W_fc  = (const float*)d_in[14];
    const float* b_fc  = (const float*)d_in[15];
    float* out = (float*)d_out;

    float* bufA; cudaGetSymbolAddress((void**)&bufA, g_bufA);
    float* h1;   cudaGetSymbolAddress((void**)&h1, g_h1);
    float* h2;   cudaGetSymbolAddress((void**)&h2, g_h2);
    __nv_bfloat16 *aggxh, *aggxl, *agg2h, *agg2l, *combh, *combl, *wth, *wtl;
    cudaGetSymbolAddress((void**)&aggxh, g_aggxh);
    cudaGetSymbolAddress((void**)&aggxl, g_aggxl);
    cudaGetSymbolAddress((void**)&agg2h, g_agg2h);
    cudaGetSymbolAddress((void**)&agg2l, g_agg2l);
    cudaGetSymbolAddress((void**)&combh, g_combh);
    cudaGetSymbolAddress((void**)&combl, g_combl);
    cudaGetSymbolAddress((void**)&wth, g_wth);
    cudaGetSymbolAddress((void**)&wtl, g_wtl);

    const int SM128 = 2 * (128 * 128 * 2) + 2 * (128 * 128 * 2);  // 131072
    const int SM64  = 2 * (128 * 256 * 2) + 2 * (64 * 256 * 2);   // 196608
    static bool attr_done = false;
    if (!attr_done) {
        cudaFuncSetAttribute(k_mma<128, 128>, cudaFuncAttributeMaxDynamicSharedMemorySize, SM128);
        cudaFuncSetAttribute(k_mma<64, 256>,  cudaFuncAttributeMaxDynamicSharedMemorySize, SM64);
        attr_done = true;
    }

    const int TB = 256;
    k_detect_init<<<(N_NODES + TB - 1) / TB, TB>>>(ei32);           // 0
    k_extract_count<<<(N_EDGES + TB - 1) / TB, TB>>>(ei32);         // 1
    k_scan_dinv<<<1, 1024>>>();                                     // 2
    k_fill<<<(N_EDGES + TB - 1) / TB, TB>>>();                      // 3

    {
        PrepB p;
        p.W[0] = W_s1;  p.K[0] = 128; p.N[0] = 128;
        p.W[1] = W_m21; p.K[1] = 128; p.N[1] = 128;
        p.W[2] = W_m1;  p.K[2] = 128; p.N[2] = 128;
        p.W[3] = W_s2;  p.K[3] = 128; p.N[3] = 128;
        p.W[4] = W_m22; p.K[4] = 128; p.N[4] = 128;
        p.W[5] = W_fc;  p.K[5] = 256; p.N[5] = 64;
        k_prepB<<<6, 256>>>(p);                                     // 4
    }

    k_agg128<<<N_NODES, 128>>>(x, aggxh, aggxl);                    // 5 (profiled)

    {
        MJobs j = {};
        for (int q = 0; q < 3; q++) { j.Ah[q] = aggxh; j.Al[q] = aggxl; j.lda[q] = 128; j.split[q] = 0; }
        j.Bh[0] = wth + 0 * 16384; j.Bl[0] = wtl + 0 * 16384; j.bias[0] = b_s1;  j.C[0] = bufA;       j.ldc[0] = 256;
        j.Bh[1] = wth + 1 * 16384; j.Bl[1] = wtl + 1 * 16384; j.bias[1] = b_m21; j.C[1] = bufA + 128; j.ldc[1] = 256;
        j.Bh[2] = wth + 2 * 16384; j.Bl[2] = wtl + 2 * 16384; j.bias[2] = b_m1;  j.C[2] = h1;         j.ldc[2] = 128;
        k_mma<128, 128><<<dim3(1, NTILES, 3), 256, SM128>>>(j, 1);  // 6
    }

    k_agg256<<<N_NODES, 256>>>(bufA, agg2h, agg2l);                 // 7

    {
        MJobs j = {};
        j.Ah[0] = agg2h;       j.Al[0] = agg2l;       j.lda[0] = 256;
        j.Ah[1] = agg2h + 128; j.Al[1] = agg2l + 128; j.lda[1] = 256;
        j.Ah[2] = j.Ah[0];     j.Al[2] = j.Al[0];     j.lda[2] = 256;
        // job0: h_struct -> comb[:, :128] as SPLIT bf16
        j.Bh[0] = wth + 3 * 16384; j.Bl[0] = wtl + 3 * 16384; j.bias[0] = b_s2;
        j.Cbh[0] = combh; j.Cbl[0] = combl; j.ldc[0] = 256; j.split[0] = 1;
        // job1: h2 fp32
        j.Bh[1] = wth + 4 * 16384; j.Bl[1] = wtl + 4 * 16384; j.bias[1] = b_m22;
        j.C[1] = h2; j.ldc[1] = 128; j.split[1] = 0;
        j.Bh[2] = j.Bh[0]; j.Bl[2] = j.Bl[0]; j.bias[2] = j.bias[0];
        j.Cbh[2] = j.Cbh[0]; j.Cbl[2] = j.Cbl[0]; j.ldc[2] = j.ldc[0]; j.split[2] = 1;
        k_mma<128, 128><<<dim3(1, NTILES, 2), 256, SM128>>>(j, 1);  // 8
    }

    k_attn<<<N_NODES / 2, 256>>>(W_att, b_att);                     // 9

    {
        MJobs j = {};
        for (int q = 0; q < 3; q++) {
            j.Ah[q] = combh; j.Al[q] = combl; j.lda[q] = 256;
            j.Bh[q] = wth + 5 * 16384; j.Bl[q] = wtl + 5 * 16384;
            j.bias[q] = b_fc; j.C[q] = out; j.ldc[q] = 64; j.split[q] = 0;
        }
        k_mma<64, 256><<<dim3(1, NTILES, 1), 256, SM64>>>(j, 0);    // 10
    }

    (void)in_sizes; (void)n_in; (void)out_size;
}

// round 7
// speedup vs baseline: 1.0918x; 1.0891x over previous
#include <cuda_runtime.h>
#include <cuda_bf16.h>
#include <math.h>
#include <cstdint>

#define N_NODES 50000
#define N_EDGES 800000
#define NTILES  391          // ceil(50000/128)

// ================= scratch =================
__device__ int   g_is64;
__device__ int   g_src[N_EDGES];
__device__ int   g_dst[N_EDGES];
__device__ int   g_edeg[N_NODES];
__device__ float g_dinv[N_NODES];
__device__ int   g_rowptr[N_NODES + 1];
__device__ int   g_cursor[N_NODES];
__device__ int   g_col[N_EDGES];
__device__ float g_wedge[N_EDGES];

__device__ float g_bufA[N_NODES * 256];   // [h_s1 | h2a] fp32 (feeds agg256)
__device__ float g_h1[N_NODES * 128];
__device__ float g_h2[N_NODES * 128];

// bf16 split operands (plain row-major)
__device__ __nv_bfloat16 g_aggxh[N_NODES * 128];
__device__ __nv_bfloat16 g_aggxl[N_NODES * 128];
__device__ __nv_bfloat16 g_agg2h[N_NODES * 256];
__device__ __nv_bfloat16 g_agg2l[N_NODES * 256];
__device__ __nv_bfloat16 g_combh[N_NODES * 256];  // [h_struct | h_meta] split
__device__ __nv_bfloat16 g_combl[N_NODES * 256];
__device__ __nv_bfloat16 g_wth[6][16384];
__device__ __nv_bfloat16 g_wtl[6][16384];

// ================= helpers =================
__device__ __forceinline__ uint32_t smem_u32(const void* p) {
    uint32_t a;
    asm("{ .reg .u64 t; cvta.to.shared.u64 t, %1; cvt.u32.u64 %0, t; }" : "=r"(a) : "l"(p));
    return a;
}
__device__ __forceinline__ void ldsm_x4(uint32_t* r, uint32_t addr) {
    asm volatile("ldmatrix.sync.aligned.m8n8.x4.shared.b16 {%0,%1,%2,%3}, [%4];"
                 : "=r"(r[0]), "=r"(r[1]), "=r"(r[2]), "=r"(r[3]) : "r"(addr));
}
__device__ __forceinline__ void ldsm_x2(uint32_t* r, uint32_t addr) {
    asm volatile("ldmatrix.sync.aligned.m8n8.x2.shared.b16 {%0,%1}, [%2];"
                 : "=r"(r[0]), "=r"(r[1]) : "r"(addr));
}
__device__ __forceinline__ void mma_bf16(float* d, const uint32_t* a, const uint32_t* b) {
    asm volatile("mma.sync.aligned.m16n8k16.row.col.f32.bf16.bf16.f32 "
                 "{%0,%1,%2,%3}, {%4,%5,%6,%7}, {%8,%9}, {%0,%1,%2,%3};"
                 : "+f"(d[0]), "+f"(d[1]), "+f"(d[2]), "+f"(d[3])
                 : "r"(a[0]), "r"(a[1]), "r"(a[2]), "r"(a[3]), "r"(b[0]), "r"(b[1]));
}
__device__ __forceinline__ void split_bf16(float v, __nv_bfloat16& h, __nv_bfloat16& l) {
    __nv_bfloat16 hb = __float2bfloat16(v);
    h = hb;
    l = __float2bfloat16(v - __bfloat162float(hb));
}

// ================= fused detect + edeg zero =================
__global__ void k_detect_init(const int* __restrict__ ei32) {
    int i = blockIdx.x * blockDim.x + threadIdx.x;
    if (i < N_NODES) g_edeg[i] = 0;
    if (blockIdx.x == 0) {
        __shared__ int nz;
        if (threadIdx.x == 0) nz = 0;
        __syncthreads();
        int local = 0;
        for (int q = threadIdx.x; q < 2048; q += blockDim.x)
            if (ei32[2 * q + 1] != 0) local = 1;
        if (local) atomicOr(&nz, 1);
        __syncthreads();
        if (threadIdx.x == 0) g_is64 = nz ? 0 : 1;
    }
}

// ================= fused extract + count =================
__global__ void k_extract_count(const int* __restrict__ ei32) {
    int e = blockIdx.x * blockDim.x + threadIdx.x;
    if (e < N_EDGES) {
        int s, d;
        if (g_is64) { s = ei32[2 * e]; d = ei32[2 * (N_EDGES + e)]; }
        else        { s = ei32[e];     d = ei32[N_EDGES + e]; }
        g_src[e] = s; g_dst[e] = d;
        atomicAdd(&g_edeg[d], 1);
    }
}

// ================= fused scan + dinv =================
__global__ void k_scan_dinv() {
    __shared__ int part[1024];
    const int t = threadIdx.x;
    const int CH = (N_NODES + 1023) / 1024;
    int start = t * CH;
    int s = 0;
    for (int i = 0; i < CH; i++) { int idx = start + i; if (idx < N_NODES) s += g_edeg[idx]; }
    part[t] = s;
    __syncthreads();
    for (int off = 1; off < 1024; off <<= 1) {
        int v = (t >= off) ? part[t - off] : 0;
        __syncthreads();
        part[t] += v;
        __syncthreads();
    }
    int run = (t == 0) ? 0 : part[t - 1];
    for (int i = 0; i < CH; i++) {
        int idx = start + i;
        if (idx < N_NODES) {
            g_rowptr[idx] = run;
            g_cursor[idx] = run;
            g_dinv[idx] = rsqrtf((float)(g_edeg[idx] + 1));
            run += g_edeg[idx];
        }
    }
    if (t == 1023) g_rowptr[N_NODES] = run;
}

__global__ void k_fill() {
    int e = blockIdx.x * blockDim.x + threadIdx.x;
    if (e < N_EDGES) {
        int s = g_src[e], d = g_dst[e];
        int p = atomicAdd(&g_cursor[d], 1);
        g_col[p] = s;
        g_wedge[p] = g_dinv[s] * g_dinv[d];
    }
}

// weights -> transposed split: Wt[n][k] from W[k][n]
struct PrepB { const float* W[6]; int K[6]; int N[6]; };
__global__ void k_prepB(PrepB p) {
    int b = blockIdx.x;
    const float* W = p.W[b];
    int K = p.K[b], N = p.N[b];
    for (int idx = threadIdx.x; idx < K * N; idx += blockDim.x) {
        int k = idx / N, n = idx % N;
        split_bf16(W[idx], g_wth[b][n * K + k], g_wtl[b][n * K + k]);
    }
}

// ================= warp-per-node aggregation =================
// agg128: warp handles one node; lane owns 4 channels (float4).
__global__ __launch_bounds__(256, 8) void k_agg128(const float* __restrict__ in,
                         __nv_bfloat16* __restrict__ oh, __nv_bfloat16* __restrict__ ol) {
    const int warp = threadIdx.x >> 5, lane = threadIdx.x & 31;
    const int n = blockIdx.x * 8 + warp;
    const int c4 = lane * 4;
    float dn = g_dinv[n];
    float4 self = *reinterpret_cast<const float4*>(in + (size_t)n * 128 + c4);
    float4 acc;
    acc.x = dn * dn * self.x; acc.y = dn * dn * self.y;
    acc.z = dn * dn * self.z; acc.w = dn * dn * self.w;
    const int beg = g_rowptr[n], end = g_rowptr[n + 1];
    for (int base = beg; base < end; base += 32) {
        int cnt = end - base; if (cnt > 32) cnt = 32;
        int   col = 0; float wt = 0.0f;
        if (lane < cnt) { col = g_col[base + lane]; wt = g_wedge[base + lane]; }
        for (int j = 0; j < cnt; j++) {
            int   idx = __shfl_sync(0xFFFFFFFFu, col, j);
            float ww  = __shfl_sync(0xFFFFFFFFu, wt,  j);
            float4 v = *reinterpret_cast<const float4*>(in + (size_t)idx * 128 + c4);
            acc.x += ww * v.x; acc.y += ww * v.y; acc.z += ww * v.z; acc.w += ww * v.w;
        }
    }
    __nv_bfloat16 h0, l0, h1, l1, h2, l2, h3, l3;
    split_bf16(acc.x, h0, l0); split_bf16(acc.y, h1, l1);
    split_bf16(acc.z, h2, l2); split_bf16(acc.w, h3, l3);
    *reinterpret_cast<__nv_bfloat162*>(oh + (size_t)n * 128 + c4)     = __nv_bfloat162{h0, h1};
    *reinterpret_cast<__nv_bfloat162*>(oh + (size_t)n * 128 + c4 + 2) = __nv_bfloat162{h2, h3};
    *reinterpret_cast<__nv_bfloat162*>(ol + (size_t)n * 128 + c4)     = __nv_bfloat162{l0, l1};
    *reinterpret_cast<__nv_bfloat162*>(ol + (size_t)n * 128 + c4 + 2) = __nv_bfloat162{l2, l3};
}

// agg256: warp per node; lane owns 8 channels (2x float4).
__global__ __launch_bounds__(256, 8) void k_agg256(const float* __restrict__ in,
                         __nv_bfloat16* __restrict__ oh, __nv_bfloat16* __restrict__ ol) {
    const int warp = threadIdx.x >> 5, lane = threadIdx.x & 31;
    const int n = blockIdx.x * 8 + warp;
    const int c8 = lane * 8;
    float dn = g_dinv[n];
    const float* rowp = in + (size_t)n * 256 + c8;
    float4 sa = *reinterpret_cast<const float4*>(rowp);
    float4 sb = *reinterpret_cast<const float4*>(rowp + 4);
    float4 accA, accB;
    accA.x = dn * dn * sa.x; accA.y = dn * dn * sa.y; accA.z = dn * dn * sa.z; accA.w = dn * dn * sa.w;
    accB.x = dn * dn * sb.x; accB.y = dn * dn * sb.y; accB.z = dn * dn * sb.z; accB.w = dn * dn * sb.w;
    const int beg = g_rowptr[n], end = g_rowptr[n + 1];
    for (int base = beg; base < end; base += 32) {
        int cnt = end - base; if (cnt > 32) cnt = 32;
        int   col = 0; float wt = 0.0f;
        if (lane < cnt) { col = g_col[base + lane]; wt = g_wedge[base + lane]; }
        for (int j = 0; j < cnt; j++) {
            int   idx = __shfl_sync(0xFFFFFFFFu, col, j);
            float ww  = __shfl_sync(0xFFFFFFFFu, wt,  j);
            const float* gp = in + (size_t)idx * 256 + c8;
            float4 va = *reinterpret_cast<const float4*>(gp);
            float4 vb = *reinterpret_cast<const float4*>(gp + 4);
            accA.x += ww * va.x; accA.y += ww * va.y; accA.z += ww * va.z; accA.w += ww * va.w;
            accB.x += ww * vb.x; accB.y += ww * vb.y; accB.z += ww * vb.z; accB.w += ww * vb.w;
        }
    }
    __nv_bfloat162 hv[4], lv[4];
    {
        __nv_bfloat16 h0, l0, h1, l1;
        split_bf16(accA.x, h0, l0); split_bf16(accA.y, h1, l1); hv[0] = {h0, h1}; lv[0] = {l0, l1};
        split_bf16(accA.z, h0, l0); split_bf16(accA.w, h1, l1); hv[1] = {h0, h1}; lv[1] = {l0, l1};
        split_bf16(accB.x, h0, l0); split_bf16(accB.y, h1, l1); hv[2] = {h0, h1}; lv[2] = {l0, l1};
        split_bf16(accB.z, h0, l0); split_bf16(accB.w, h1, l1); hv[3] = {h0, h1}; lv[3] = {l0, l1};
    }
    *reinterpret_cast<uint4*>(oh + (size_t)n * 256 + c8) = *reinterpret_cast<uint4*>(hv);
    *reinterpret_cast<uint4*>(ol + (size_t)n * 256 + c8) = *reinterpret_cast<uint4*>(lv);
}

// ================= split-bf16 mma.sync GEMM =================
struct MJobs {
    const __nv_bfloat16* Ah[3];
    const __nv_bfloat16* Al[3];
    const __nv_bfloat16* Bh[3];
    const __nv_bfloat16* Bl[3];
    const float*         bias[3];
    float*               C[3];
    __nv_bfloat16*       Cbh[3];
    __nv_bfloat16*       Cbl[3];
    int                  lda[3];
    int                  ldc[3];
    int                  split[3];
};

template <int NN, int KK>
__global__ __launch_bounds__(256, 1) void k_mma(MJobs jobs, int do_relu) {
    extern __shared__ __align__(16) unsigned char smem[];
    constexpr int NCH = KK / 8;
    constexpr int AB  = 128 * KK * 2;
    constexpr int BB  = NN * KK * 2;
    constexpr int NI  = NN / 32;
    constexpr int KSTEPS = KK / 16;

    const int job = blockIdx.z;
    const int bm  = blockIdx.y * 128;
    const int tid = threadIdx.x;
    const int lane = tid & 31, warp = tid >> 5;
    const int wm = (warp >> 2) * 64;
    const int wn = (warp & 3) * (NN / 4);

    const __nv_bfloat16* Ah = jobs.Ah[job];
    const __nv_bfloat16* Al = jobs.Al[job];
    const int lda = jobs.lda[job];

    {
        const int ldach = lda / 8;
        uint4* s = reinterpret_cast<uint4*>(smem);
        for (int idx = tid; idx < 128 * NCH; idx += 256) {
            int r = idx / NCH, cc = idx % NCH;
            long gr = bm + r; if (gr >= N_NODES) gr = N_NODES - 1;
            int sp = r * NCH + (cc ^ (r & 7));
            s[sp]           = reinterpret_cast<const uint4*>(Ah)[gr * ldach + cc];
            s[sp + AB / 16] = reinterpret_cast<const uint4*>(Al)[gr * ldach + cc];
        }
        const uint4* bh = reinterpret_cast<const uint4*>(jobs.Bh[job]);
        const uint4* bl = reinterpret_cast<const uint4*>(jobs.Bl[job]);
        uint4* sb = reinterpret_cast<uint4*>(smem + 2 * AB);
        for (int idx = tid; idx < NN * NCH; idx += 256) {
            int r = idx / NCH, cc = idx % NCH;
            int sp = r * NCH + (cc ^ (r & 7));
            sb[sp]           = bh[idx];
            sb[sp + BB / 16] = bl[idx];
        }
    }
    __syncthreads();

    const uint32_t sbase = smem_u32(smem);
    const int group = lane >> 3, within = lane & 7;
    const int kaddA = group >> 1;
    uint32_t abyte[4]; int rx[4];
    {
        int mrow = wm + (group & 1) * 8 + within;
#pragma unroll
        for (int mi = 0; mi < 4; mi++) {
            int r = mrow + mi * 16;
            abyte[mi] = (uint32_t)(r * NCH) << 4;
            rx[mi] = r & 7;
        }
    }
    const int laneB = lane & 15;
    const int kaddB = laneB >> 3, withinB = laneB & 7;
    uint32_t bbyte[NI]; int nx[NI];
#pragma unroll
    for (int ni = 0; ni < NI; ni++) {
        int r = wn + ni * 8 + withinB;
        bbyte[ni] = (uint32_t)(r * NCH) << 4;
        nx[ni] = r & 7;
    }

    float acc[4][NI][4];
#pragma unroll
    for (int mi = 0; mi < 4; mi++)
#pragma unroll
        for (int ni = 0; ni < NI; ni++)
#pragma unroll
            for (int q = 0; q < 4; q++) acc[mi][ni][q] = 0.0f;

#pragma unroll 1
    for (int pass = 0; pass < 3; pass++) {
        const uint32_t aoff = sbase + (pass == 2 ? AB : 0);
        const uint32_t boff = sbase + 2 * AB + (pass == 1 ? BB : 0);
#pragma unroll
        for (int s = 0; s < KSTEPS; s++) {
            const int kc = s * 2;
            uint32_t bf[NI][2];
#pragma unroll
            for (int ni = 0; ni < NI; ni++)
                ldsm_x2(bf[ni], boff + bbyte[ni] + ((uint32_t)((kc + kaddB) ^ nx[ni]) << 4));
#pragma unroll
            for (int mi = 0; mi < 4; mi++) {
                uint32_t af[4];
                ldsm_x4(af, aoff + abyte[mi] + ((uint32_t)((kc + kaddA) ^ rx[mi]) << 4));
#pragma unroll
                for (int ni = 0; ni < NI; ni++)
                    mma_bf16(acc[mi][ni], af, bf[ni]);
            }
        }
    }

    const float* bias = jobs.bias[job];
    float* C = jobs.C[job];
    __nv_bfloat16* Cbh = jobs.Cbh[job];
    __nv_bfloat16* Cbl = jobs.Cbl[job];
    const int ldc = jobs.ldc[job];
    const int splt = jobs.split[job];
    const int g = lane >> 2, tc = lane & 3;
#pragma unroll
    for (int mi = 0; mi < 4; mi++) {
#pragma unroll
        for (int ni = 0; ni < NI; ni++) {
            int n0 = wn + ni * 8 + tc * 2;
            float b0 = bias[n0], b1 = bias[n0 + 1];
            int m0 = bm + wm + mi * 16 + g;
            float v0 = acc[mi][ni][0] + b0, v1 = acc[mi][ni][1] + b1;
            float v2 = acc[mi][ni][2] + b0, v3 = acc[mi][ni][3] + b1;
            if (do_relu) {
                v0 = fmaxf(v0, 0.0f); v1 = fmaxf(v1, 0.0f);
                v2 = fmaxf(v2, 0.0f); v3 = fmaxf(v3, 0.0f);
            }
            if (splt) {
                __nv_bfloat16 h0, l0, h1b, l1;
                if (m0 < N_NODES) {
                    split_bf16(v0, h0, l0); split_bf16(v1, h1b, l1);
                    *reinterpret_cast<__nv_bfloat162*>(Cbh + (size_t)m0 * ldc + n0) = __nv_bfloat162{h0, h1b};
                    *reinterpret_cast<__nv_bfloat162*>(Cbl + (size_t)m0 * ldc + n0) = __nv_bfloat162{l0, l1};
                }
                if (m0 + 8 < N_NODES) {
                    split_bf16(v2, h0, l0); split_bf16(v3, h1b, l1);
                    *reinterpret_cast<__nv_bfloat162*>(Cbh + (size_t)(m0 + 8) * ldc + n0) = __nv_bfloat162{h0, h1b};
                    *reinterpret_cast<__nv_bfloat162*>(Cbl + (size_t)(m0 + 8) * ldc + n0) = __nv_bfloat162{l0, l1};
                }
            } else {
                if (m0 < N_NODES)
                    *reinterpret_cast<float2*>(C + (size_t)m0 * ldc + n0) = make_float2(v0, v1);
                if (m0 + 8 < N_NODES)
                    *reinterpret_cast<float2*>(C + (size_t)(m0 + 8) * ldc + n0) = make_float2(v2, v3);
            }
        }
    }
}

// ================= attention fusion (2 nodes/block, writes split bf16 meta) =================
__global__ void k_attn(const float* __restrict__ watt, const float* __restrict__ batt) {
    const int half = threadIdx.x >> 7;
    const int c = threadIdx.x & 127;
    const int n = blockIdx.x * 2 + half;
    float h1v = g_h1[n * 128 + c];
    float h2v = g_h2[n * 128 + c];
    float wa = watt[c];
    float p1 = h1v * wa;
    float p2 = h2v * wa;
#pragma unroll
    for (int o = 16; o > 0; o >>= 1) {
        p1 += __shfl_down_sync(0xFFFFFFFFu, p1, o);
        p2 += __shfl_down_sync(0xFFFFFFFFu, p2, o);
    }
    __shared__ float s1[8], s2[8];
    __shared__ float a1s[2];
    int w = threadIdx.x >> 5;
    if ((threadIdx.x & 31) == 0) { s1[w] = p1; s2[w] = p2; }
    __syncthreads();
    if (c == 0) {
        int b = half * 4;
        float S1 = s1[b] + s1[b+1] + s1[b+2] + s1[b+3] + batt[0];
        float S2 = s2[b] + s2[b+1] + s2[b+2] + s2[b+3] + batt[0];
        a1s[half] = 1.0f / (1.0f + expf(S2 - S1));
    }
    __syncthreads();
    float a1 = a1s[half];
    float v = a1 * h1v + (1.0f - a1) * h2v;
    __nv_bfloat16 h, l;
    split_bf16(v, h, l);
    g_combh[n * 256 + 128 + c] = h;
    g_combl[n * 256 + 128 + c] = l;
}

// ================= launch =================
extern "C" void kernel_launch(void* const* d_in, const int* in_sizes, int n_in,
                              void* d_out, int out_size) {
    const float* x    = (const float*)d_in[0];
    const int*   ei32 = (const int*)d_in[1];
    const float* W_s1 = (const float*)d_in[2];
    const float* b_s1 = (const float*)d_in[3];
    const float* W_s2 = (const float*)d_in[4];
    const float* b_s2 = (const float*)d_in[5];
    const float* W_m1 = (const float*)d_in[6];
    const float* b_m1 = (const float*)d_in[7];
    const float* W_m21 = (const float*)d_in[8];
    const float* b_m21 = (const float*)d_in[9];
    const float* W_m22 = (const float*)d_in[10];
    const float* b_m22 = (const float*)d_in[11];
    const float* W_att = (const float*)d_in[12];
    const float* b_att = (const float*)d_in[13];
    const float* W_fc  = (const float*)d_in[14];
    const float* b_fc  = (const float*)d_in[15];
    float* out = (float*)d_out;

    float* bufA; cudaGetSymbolAddress((void**)&bufA, g_bufA);
    float* h1;   cudaGetSymbolAddress((void**)&h1, g_h1);
    float* h2;   cudaGetSymbolAddress((void**)&h2, g_h2);
    __nv_bfloat16 *aggxh, *aggxl, *agg2h, *agg2l, *combh, *combl, *wth, *wtl;
    cudaGetSymbolAddress((void**)&aggxh, g_aggxh);
    cudaGetSymbolAddress((void**)&aggxl, g_aggxl);
    cudaGetSymbolAddress((void**)&agg2h, g_agg2h);
    cudaGetSymbolAddress((void**)&agg2l, g_agg2l);
    cudaGetSymbolAddress((void**)&combh, g_combh);
    cudaGetSymbolAddress((void**)&combl, g_combl);
    cudaGetSymbolAddress((void**)&wth, g_wth);
    cudaGetSymbolAddress((void**)&wtl, g_wtl);

    const int SM128 = 2 * (128 * 128 * 2) + 2 * (128 * 128 * 2);  // 131072
    const int SM64  = 2 * (128 * 256 * 2) + 2 * (64 * 256 * 2);   // 196608
    static bool attr_done = false;
    if (!attr_done) {
        cudaFuncSetAttribute(k_mma<128, 128>, cudaFuncAttributeMaxDynamicSharedMemorySize, SM128);
        cudaFuncSetAttribute(k_mma<64, 256>,  cudaFuncAttributeMaxDynamicSharedMemorySize, SM64);
        attr_done = true;
    }

    const int TB = 256;
    k_detect_init<<<(N_NODES + TB - 1) / TB, TB>>>(ei32);
    k_extract_count<<<(N_EDGES + TB - 1) / TB, TB>>>(ei32);
    k_scan_dinv<<<1, 1024>>>();
    k_fill<<<(N_EDGES + TB - 1) / TB, TB>>>();

    {
        PrepB p;
        p.W[0] = W_s1;  p.K[0] = 128; p.N[0] = 128;
        p.W[1] = W_m21; p.K[1] = 128; p.N[1] = 128;
        p.W[2] = W_m1;  p.K[2] = 128; p.N[2] = 128;
        p.W[3] = W_s2;  p.K[3] = 128; p.N[3] = 128;
        p.W[4] = W_m22; p.K[4] = 128; p.N[4] = 128;
        p.W[5] = W_fc;  p.K[5] = 256; p.N[5] = 64;
        k_prepB<<<6, 256>>>(p);
    }

    // warp-per-node aggregation: 8 nodes per 256-thread CTA
    k_agg128<<<N_NODES / 8, 256>>>(x, aggxh, aggxl);

    {
        MJobs j = {};
        for (int q = 0; q < 3; q++) { j.Ah[q] = aggxh; j.Al[q] = aggxl; j.lda[q] = 128; j.split[q] = 0; }
        j.Bh[0] = wth + 0 * 16384; j.Bl[0] = wtl + 0 * 16384; j.bias[0] = b_s1;  j.C[0] = bufA;       j.ldc[0] = 256;
        j.Bh[1] = wth + 1 * 16384; j.Bl[1] = wtl + 1 * 16384; j.bias[1] = b_m21; j.C[1] = bufA + 128; j.ldc[1] = 256;
        j.Bh[2] = wth + 2 * 16384; j.Bl[2] = wtl + 2 * 16384; j.bias[2] = b_m1;  j.C[2] = h1;         j.ldc[2] = 128;
        k_mma<128, 128><<<dim3(1, NTILES, 3), 256, SM128>>>(j, 1);
    }

    k_agg256<<<N_NODES / 8, 256>>>(bufA, agg2h, agg2l);

    {
        MJobs j = {};
        j.Ah[0] = agg2h;       j.Al[0] = agg2l;       j.lda[0] = 256;
        j.Ah[1] = agg2h + 128; j.Al[1] = agg2l + 128; j.lda[1] = 256;
        j.Ah[2] = j.Ah[0];     j.Al[2] = j.Al[0];     j.lda[2] = 256;
        j.Bh[0] = wth + 3 * 16384; j.Bl[0] = wtl + 3 * 16384; j.bias[0] = b_s2;
        j.Cbh[0] = combh; j.Cbl[0] = combl; j.ldc[0] = 256; j.split[0] = 1;
        j.Bh[1] = wth + 4 * 16384; j.Bl[1] = wtl + 4 * 16384; j.bias[1] = b_m22;
        j.C[1] = h2; j.ldc[1] = 128; j.split[1] = 0;
        j.Bh[2] = j.Bh[0]; j.Bl[2] = j.Bl[0]; j.bias[2] = j.bias[0];
        j.Cbh[2] = j.Cbh[0]; j.Cbl[2] = j.Cbl[0]; j.ldc[2] = j.ldc[0]; j.split[2] = 1;
        k_mma<128, 128><<<dim3(1, NTILES, 2), 256, SM128>>>(j, 1);
    }

    k_attn<<<N_NODES / 2, 256>>>(W_att, b_att);

    {
        MJobs j = {};
        for (int q = 0; q < 3; q++) {
            j.Ah[q] = combh; j.Al[q] = combl; j.lda[q] = 256;
            j.Bh[q] = wth + 5 * 16384; j.Bl[q] = wtl + 5 * 16384;
            j.bias[q] = b_fc; j.C[q] = out; j.ldc[q] = 64; j.split[q] = 0;
        }
        k_mma<64, 256><<<dim3(1, NTILES, 1), 256, SM64>>>(j, 0);
    }

    (void)in_sizes; (void)n_in; (void)out_size;
}

// round 8
// speedup vs baseline: 1.1947x; 1.0942x over previous
#include <cuda_runtime.h>
#include <cuda_bf16.h>
#include <math.h>
#include <cstdint>

#define N_NODES 50000
#define N_EDGES 800000

// ================= scratch =================
__device__ int   g_is64;
__device__ int   g_src[N_EDGES];
__device__ int   g_dst[N_EDGES];
__device__ int   g_edeg[N_NODES];
__device__ float g_dinv[N_NODES];
__device__ int   g_rowptr[N_NODES + 1];
__device__ int   g_cursor[N_NODES];
__device__ int   g_col[N_EDGES];
__device__ float g_wedge[N_EDGES];

__device__ float g_bufA[N_NODES * 256];   // [h_s1 | h2a] fp32 (feeds agg256)
__device__ float g_h1[N_NODES * 128];
__device__ float g_h2[N_NODES * 128];

// bf16 split operands (plain row-major)
__device__ __nv_bfloat16 g_aggxh[N_NODES * 128];
__device__ __nv_bfloat16 g_aggxl[N_NODES * 128];
__device__ __nv_bfloat16 g_agg2h[N_NODES * 256];
__device__ __nv_bfloat16 g_agg2l[N_NODES * 256];
__device__ __nv_bfloat16 g_combh[N_NODES * 256];  // [h_struct | h_meta] split
__device__ __nv_bfloat16 g_combl[N_NODES * 256];
__device__ __nv_bfloat16 g_wth[6][16384];
__device__ __nv_bfloat16 g_wtl[6][16384];

// ================= helpers =================
__device__ __forceinline__ uint32_t smem_u32(const void* p) {
    uint32_t a;
    asm("{ .reg .u64 t; cvta.to.shared.u64 t, %1; cvt.u32.u64 %0, t; }" : "=r"(a) : "l"(p));
    return a;
}
__device__ __forceinline__ void ldsm_x4(uint32_t* r, uint32_t addr) {
    asm volatile("ldmatrix.sync.aligned.m8n8.x4.shared.b16 {%0,%1,%2,%3}, [%4];"
                 : "=r"(r[0]), "=r"(r[1]), "=r"(r[2]), "=r"(r[3]) : "r"(addr));
}
__device__ __forceinline__ void ldsm_x2(uint32_t* r, uint32_t addr) {
    asm volatile("ldmatrix.sync.aligned.m8n8.x2.shared.b16 {%0,%1}, [%2];"
                 : "=r"(r[0]), "=r"(r[1]) : "r"(addr));
}
__device__ __forceinline__ void mma_bf16(float* d, const uint32_t* a, const uint32_t* b) {
    asm volatile("mma.sync.aligned.m16n8k16.row.col.f32.bf16.bf16.f32 "
                 "{%0,%1,%2,%3}, {%4,%5,%6,%7}, {%8,%9}, {%0,%1,%2,%3};"
                 : "+f"(d[0]), "+f"(d[1]), "+f"(d[2]), "+f"(d[3])
                 : "r"(a[0]), "r"(a[1]), "r"(a[2]), "r"(a[3]), "r"(b[0]), "r"(b[1]));
}
__device__ __forceinline__ void split_bf16(float v, __nv_bfloat16& h, __nv_bfloat16& l) {
    __nv_bfloat16 hb = __float2bfloat16(v);
    h = hb;
    l = __float2bfloat16(v - __bfloat162float(hb));
}

// ================= fused detect + edeg zero =================
__global__ void k_detect_init(const int* __restrict__ ei32) {
    int i = blockIdx.x * blockDim.x + threadIdx.x;
    if (i < N_NODES) g_edeg[i] = 0;
    if (blockIdx.x == 0) {
        __shared__ int nz;
        if (threadIdx.x == 0) nz = 0;
        __syncthreads();
        int local = 0;
        for (int q = threadIdx.x; q < 2048; q += blockDim.x)
            if (ei32[2 * q + 1] != 0) local = 1;
        if (local) atomicOr(&nz, 1);
        __syncthreads();
        if (threadIdx.x == 0) g_is64 = nz ? 0 : 1;
    }
}

// ================= fused extract + count =================
__global__ void k_extract_count(const int* __restrict__ ei32) {
    int e = blockIdx.x * blockDim.x + threadIdx.x;
    if (e < N_EDGES) {
        int s, d;
        if (g_is64) { s = ei32[2 * e]; d = ei32[2 * (N_EDGES + e)]; }
        else        { s = ei32[e];     d = ei32[N_EDGES + e]; }
        g_src[e] = s; g_dst[e] = d;
        atomicAdd(&g_edeg[d], 1);
    }
}

// ================= fused scan + dinv =================
__global__ void k_scan_dinv() {
    __shared__ int part[1024];
    const int t = threadIdx.x;
    const int CH = (N_NODES + 1023) / 1024;
    int start = t * CH;
    int s = 0;
    for (int i = 0; i < CH; i++) { int idx = start + i; if (idx < N_NODES) s += g_edeg[idx]; }
    part[t] = s;
    __syncthreads();
    for (int off = 1; off < 1024; off <<= 1) {
        int v = (t >= off) ? part[t - off] : 0;
        __syncthreads();
        part[t] += v;
        __syncthreads();
    }
    int run = (t == 0) ? 0 : part[t - 1];
    for (int i = 0; i < CH; i++) {
        int idx = start + i;
        if (idx < N_NODES) {
            g_rowptr[idx] = run;
            g_cursor[idx] = run;
            g_dinv[idx] = rsqrtf((float)(g_edeg[idx] + 1));
            run += g_edeg[idx];
        }
    }
    if (t == 1023) g_rowptr[N_NODES] = run;
}

__global__ void k_fill() {
    int e = blockIdx.x * blockDim.x + threadIdx.x;
    if (e < N_EDGES) {
        int s = g_src[e], d = g_dst[e];
        int p = atomicAdd(&g_cursor[d], 1);
        g_col[p] = s;
        g_wedge[p] = g_dinv[s] * g_dinv[d];
    }
}

// weights -> transposed split: Wt[n][k] from W[k][n]
struct PrepB { const float* W[6]; int K[6]; int N[6]; };
__global__ void k_prepB(PrepB p) {
    int b = blockIdx.x;
    const float* W = p.W[b];
    int K = p.K[b], N = p.N[b];
    for (int idx = threadIdx.x; idx < K * N; idx += blockDim.x) {
        int k = idx / N, n = idx % N;
        split_bf16(W[idx], g_wth[b][n * K + k], g_wtl[b][n * K + k]);
    }
}

// ================= warp-per-node aggregation =================
__global__ __launch_bounds__(256, 8) void k_agg128(const float* __restrict__ in,
                         __nv_bfloat16* __restrict__ oh, __nv_bfloat16* __restrict__ ol) {
    const int warp = threadIdx.x >> 5, lane = threadIdx.x & 31;
    const int n = blockIdx.x * 8 + warp;
    const int c4 = lane * 4;
    float dn = g_dinv[n];
    float4 self = *reinterpret_cast<const float4*>(in + (size_t)n * 128 + c4);
    float4 acc;
    acc.x = dn * dn * self.x; acc.y = dn * dn * self.y;
    acc.z = dn * dn * self.z; acc.w = dn * dn * self.w;
    const int beg = g_rowptr[n], end = g_rowptr[n + 1];
    for (int base = beg; base < end; base += 32) {
        int cnt = end - base; if (cnt > 32) cnt = 32;
        int   col = 0; float wt = 0.0f;
        if (lane < cnt) { col = g_col[base + lane]; wt = g_wedge[base + lane]; }
        for (int j = 0; j < cnt; j++) {
            int   idx = __shfl_sync(0xFFFFFFFFu, col, j);
            float ww  = __shfl_sync(0xFFFFFFFFu, wt,  j);
            float4 v = *reinterpret_cast<const float4*>(in + (size_t)idx * 128 + c4);
            acc.x += ww * v.x; acc.y += ww * v.y; acc.z += ww * v.z; acc.w += ww * v.w;
        }
    }
    __nv_bfloat16 h0, l0, h1, l1, h2, l2, h3, l3;
    split_bf16(acc.x, h0, l0); split_bf16(acc.y, h1, l1);
    split_bf16(acc.z, h2, l2); split_bf16(acc.w, h3, l3);
    *reinterpret_cast<__nv_bfloat162*>(oh + (size_t)n * 128 + c4)     = __nv_bfloat162{h0, h1};
    *reinterpret_cast<__nv_bfloat162*>(oh + (size_t)n * 128 + c4 + 2) = __nv_bfloat162{h2, h3};
    *reinterpret_cast<__nv_bfloat162*>(ol + (size_t)n * 128 + c4)     = __nv_bfloat162{l0, l1};
    *reinterpret_cast<__nv_bfloat162*>(ol + (size_t)n * 128 + c4 + 2) = __nv_bfloat162{l2, l3};
}

__global__ __launch_bounds__(256, 8) void k_agg256(const float* __restrict__ in,
                         __nv_bfloat16* __restrict__ oh, __nv_bfloat16* __restrict__ ol) {
    const int warp = threadIdx.x >> 5, lane = threadIdx.x & 31;
    const int n = blockIdx.x * 8 + warp;
    const int c8 = lane * 8;
    float dn = g_dinv[n];
    const float* rowp = in + (size_t)n * 256 + c8;
    float4 sa = *reinterpret_cast<const float4*>(rowp);
    float4 sb = *reinterpret_cast<const float4*>(rowp + 4);
    float4 accA, accB;
    accA.x = dn * dn * sa.x; accA.y = dn * dn * sa.y; accA.z = dn * dn * sa.z; accA.w = dn * dn * sa.w;
    accB.x = dn * dn * sb.x; accB.y = dn * dn * sb.y; accB.z = dn * dn * sb.z; accB.w = dn * dn * sb.w;
    const int beg = g_rowptr[n], end = g_rowptr[n + 1];
    for (int base = beg; base < end; base += 32) {
        int cnt = end - base; if (cnt > 32) cnt = 32;
        int   col = 0; float wt = 0.0f;
        if (lane < cnt) { col = g_col[base + lane]; wt = g_wedge[base + lane]; }
        for (int j = 0; j < cnt; j++) {
            int   idx = __shfl_sync(0xFFFFFFFFu, col, j);
            float ww  = __shfl_sync(0xFFFFFFFFu, wt,  j);
            const float* gp = in + (size_t)idx * 256 + c8;
            float4 va = *reinterpret_cast<const float4*>(gp);
            float4 vb = *reinterpret_cast<const float4*>(gp + 4);
            accA.x += ww * va.x; accA.y += ww * va.y; accA.z += ww * va.z; accA.w += ww * va.w;
            accB.x += ww * vb.x; accB.y += ww * vb.y; accB.z += ww * vb.z; accB.w += ww * vb.w;
        }
    }
    __nv_bfloat162 hv[4], lv[4];
    {
        __nv_bfloat16 h0, l0, h1, l1;
        split_bf16(accA.x, h0, l0); split_bf16(accA.y, h1, l1); hv[0] = {h0, h1}; lv[0] = {l0, l1};
        split_bf16(accA.z, h0, l0); split_bf16(accA.w, h1, l1); hv[1] = {h0, h1}; lv[1] = {l0, l1};
        split_bf16(accB.x, h0, l0); split_bf16(accB.y, h1, l1); hv[2] = {h0, h1}; lv[2] = {l0, l1};
        split_bf16(accB.z, h0, l0); split_bf16(accB.w, h1, l1); hv[3] = {h0, h1}; lv[3] = {l0, l1};
    }
    *reinterpret_cast<uint4*>(oh + (size_t)n * 256 + c8) = *reinterpret_cast<uint4*>(hv);
    *reinterpret_cast<uint4*>(ol + (size_t)n * 256 + c8) = *reinterpret_cast<uint4*>(lv);
}

// ================= split-bf16 mma.sync GEMM (BM parameterized) =================
struct MJobs {
    const __nv_bfloat16* Ah[3];
    const __nv_bfloat16* Al[3];
    const __nv_bfloat16* Bh[3];
    const __nv_bfloat16* Bl[3];
    const float*         bias[3];
    float*               C[3];
    __nv_bfloat16*       Cbh[3];
    __nv_bfloat16*       Cbl[3];
    int                  lda[3];
    int                  ldc[3];
    int                  split[3];
};

template <int BM, int NN, int KK>
__global__ __launch_bounds__(256, 2) void k_mma(MJobs jobs, int do_relu) {
    extern __shared__ __align__(16) unsigned char smem[];
    constexpr int NCH = KK / 8;
    constexpr int AB  = BM * KK * 2;
    constexpr int BB  = NN * KK * 2;
    constexpr int NI  = NN / 32;
    constexpr int MI  = BM / 32;
    constexpr int KSTEPS = KK / 16;

    const int job = blockIdx.z;
    const int bm  = blockIdx.y * BM;
    const int tid = threadIdx.x;
    const int lane = tid & 31, warp = tid >> 5;
    const int wm = (warp >> 2) * (BM / 2);
    const int wn = (warp & 3) * (NN / 4);

    const __nv_bfloat16* Ah = jobs.Ah[job];
    const __nv_bfloat16* Al = jobs.Al[job];
    const int lda = jobs.lda[job];

    {
        const int ldach = lda / 8;
        uint4* s = reinterpret_cast<uint4*>(smem);
        for (int idx = tid; idx < BM * NCH; idx += 256) {
            int r = idx / NCH, cc = idx % NCH;
            long gr = bm + r; if (gr >= N_NODES) gr = N_NODES - 1;
            int sp = r * NCH + (cc ^ (r & 7));
            s[sp]           = reinterpret_cast<const uint4*>(Ah)[gr * ldach + cc];
            s[sp + AB / 16] = reinterpret_cast<const uint4*>(Al)[gr * ldach + cc];
        }
        const uint4* bh = reinterpret_cast<const uint4*>(jobs.Bh[job]);
        const uint4* bl = reinterpret_cast<const uint4*>(jobs.Bl[job]);
        uint4* sb = reinterpret_cast<uint4*>(smem + 2 * AB);
        for (int idx = tid; idx < NN * NCH; idx += 256) {
            int r = idx / NCH, cc = idx % NCH;
            int sp = r * NCH + (cc ^ (r & 7));
            sb[sp]           = bh[idx];
            sb[sp + BB / 16] = bl[idx];
        }
    }
    __syncthreads();

    const uint32_t sbase = smem_u32(smem);
    const int group = lane >> 3, within = lane & 7;
    const int kaddA = group >> 1;
    uint32_t abyte[MI]; int rx[MI];
    {
        int mrow = wm + (group & 1) * 8 + within;
#pragma unroll
        for (int mi = 0; mi < MI; mi++) {
            int r = mrow + mi * 16;
            abyte[mi] = (uint32_t)(r * NCH) << 4;
            rx[mi] = r & 7;
        }
    }
    const int laneB = lane & 15;
    const int kaddB = laneB >> 3, withinB = laneB & 7;
    uint32_t bbyte[NI]; int nx[NI];
#pragma unroll
    for (int ni = 0; ni < NI; ni++) {
        int r = wn + ni * 8 + withinB;
        bbyte[ni] = (uint32_t)(r * NCH) << 4;
        nx[ni] = r & 7;
    }

    float acc[MI][NI][4];
#pragma unroll
    for (int mi = 0; mi < MI; mi++)
#pragma unroll
        for (int ni = 0; ni < NI; ni++)
#pragma unroll
            for (int q = 0; q < 4; q++) acc[mi][ni][q] = 0.0f;

#pragma unroll 1
    for (int pass = 0; pass < 3; pass++) {
        const uint32_t aoff = sbase + (pass == 2 ? AB : 0);
        const uint32_t boff = sbase + 2 * AB + (pass == 1 ? BB : 0);
#pragma unroll
        for (int s = 0; s < KSTEPS; s++) {
            const int kc = s * 2;
            uint32_t bf[NI][2];
#pragma unroll
            for (int ni = 0; ni < NI; ni++)
                ldsm_x2(bf[ni], boff + bbyte[ni] + ((uint32_t)((kc + kaddB) ^ nx[ni]) << 4));
#pragma unroll
            for (int mi = 0; mi < MI; mi++) {
                uint32_t af[4];
                ldsm_x4(af, aoff + abyte[mi] + ((uint32_t)((kc + kaddA) ^ rx[mi]) << 4));
#pragma unroll
                for (int ni = 0; ni < NI; ni++)
                    mma_bf16(acc[mi][ni], af, bf[ni]);
            }
        }
    }

    const float* bias = jobs.bias[job];
    float* C = jobs.C[job];
    __nv_bfloat16* Cbh = jobs.Cbh[job];
    __nv_bfloat16* Cbl = jobs.Cbl[job];
    const int ldc = jobs.ldc[job];
    const int splt = jobs.split[job];
    const int g = lane >> 2, tc = lane & 3;
#pragma unroll
    for (int mi = 0; mi < MI; mi++) {
#pragma unroll
        for (int ni = 0; ni < NI; ni++) {
            int n0 = wn + ni * 8 + tc * 2;
            float b0 = bias[n0], b1 = bias[n0 + 1];
            int m0 = bm + wm + mi * 16 + g;
            float v0 = acc[mi][ni][0] + b0, v1 = acc[mi][ni][1] + b1;
            float v2 = acc[mi][ni][2] + b0, v3 = acc[mi][ni][3] + b1;
            if (do_relu) {
                v0 = fmaxf(v0, 0.0f); v1 = fmaxf(v1, 0.0f);
                v2 = fmaxf(v2, 0.0f); v3 = fmaxf(v3, 0.0f);
            }
            if (splt) {
                __nv_bfloat16 h0, l0, h1b, l1;
                if (m0 < N_NODES) {
                    split_bf16(v0, h0, l0); split_bf16(v1, h1b, l1);
                    *reinterpret_cast<__nv_bfloat162*>(Cbh + (size_t)m0 * ldc + n0) = __nv_bfloat162{h0, h1b};
                    *reinterpret_cast<__nv_bfloat162*>(Cbl + (size_t)m0 * ldc + n0) = __nv_bfloat162{l0, l1};
                }
                if (m0 + 8 < N_NODES) {
                    split_bf16(v2, h0, l0); split_bf16(v3, h1b, l1);
                    *reinterpret_cast<__nv_bfloat162*>(Cbh + (size_t)(m0 + 8) * ldc + n0) = __nv_bfloat162{h0, h1b};
                    *reinterpret_cast<__nv_bfloat162*>(Cbl + (size_t)(m0 + 8) * ldc + n0) = __nv_bfloat162{l0, l1};
                }
            } else {
                if (m0 < N_NODES)
                    *reinterpret_cast<float2*>(C + (size_t)m0 * ldc + n0) = make_float2(v0, v1);
                if (m0 + 8 < N_NODES)
                    *reinterpret_cast<float2*>(C + (size_t)(m0 + 8) * ldc + n0) = make_float2(v2, v3);
            }
        }
    }
}

// ================= attention fusion (2 nodes/block, writes split bf16 meta) =================
__global__ void k_attn(const float* __restrict__ watt, const float* __restrict__ batt) {
    const int half = threadIdx.x >> 7;
    const int c = threadIdx.x & 127;
    const int n = blockIdx.x * 2 + half;
    float h1v = g_h1[n * 128 + c];
    float h2v = g_h2[n * 128 + c];
    float wa = watt[c];
    float p1 = h1v * wa;
    float p2 = h2v * wa;
#pragma unroll
    for (int o = 16; o > 0; o >>= 1) {
        p1 += __shfl_down_sync(0xFFFFFFFFu, p1, o);
        p2 += __shfl_down_sync(0xFFFFFFFFu, p2, o);
    }
    __shared__ float s1[8], s2[8];
    __shared__ float a1s[2];
    int w = threadIdx.x >> 5;
    if ((threadIdx.x & 31) == 0) { s1[w] = p1; s2[w] = p2; }
    __syncthreads();
    if (c == 0) {
        int b = half * 4;
        float S1 = s1[b] + s1[b+1] + s1[b+2] + s1[b+3] + batt[0];
        float S2 = s2[b] + s2[b+1] + s2[b+2] + s2[b+3] + batt[0];
        a1s[half] = 1.0f / (1.0f + expf(S2 - S1));
    }
    __syncthreads();
    float a1 = a1s[half];
    float v = a1 * h1v + (1.0f - a1) * h2v;
    __nv_bfloat16 h, l;
    split_bf16(v, h, l);
    g_combh[n * 256 + 128 + c] = h;
    g_combl[n * 256 + 128 + c] = l;
}

// ================= launch =================
extern "C" void kernel_launch(void* const* d_in, const int* in_sizes, int n_in,
                              void* d_out, int out_size) {
    const float* x    = (const float*)d_in[0];
    const int*   ei32 = (const int*)d_in[1];
    const float* W_s1 = (const float*)d_in[2];
    const float* b_s1 = (const float*)d_in[3];
    const float* W_s2 = (const float*)d_in[4];
    const float* b_s2 = (const float*)d_in[5];
    const float* W_m1 = (const float*)d_in[6];
    const float* b_m1 = (const float*)d_in[7];
    const float* W_m21 = (const float*)d_in[8];
    const float* b_m21 = (const float*)d_in[9];
    const float* W_m22 = (const float*)d_in[10];
    const float* b_m22 = (const float*)d_in[11];
    const float* W_att = (const float*)d_in[12];
    const float* b_att = (const float*)d_in[13];
    const float* W_fc  = (const float*)d_in[14];
    const float* b_fc  = (const float*)d_in[15];
    float* out = (float*)d_out;

    float* bufA; cudaGetSymbolAddress((void**)&bufA, g_bufA);
    float* h1;   cudaGetSymbolAddress((void**)&h1, g_h1);
    float* h2;   cudaGetSymbolAddress((void**)&h2, g_h2);
    __nv_bfloat16 *aggxh, *aggxl, *agg2h, *agg2l, *combh, *combl, *wth, *wtl;
    cudaGetSymbolAddress((void**)&aggxh, g_aggxh);
    cudaGetSymbolAddress((void**)&aggxl, g_aggxl);
    cudaGetSymbolAddress((void**)&agg2h, g_agg2h);
    cudaGetSymbolAddress((void**)&agg2l, g_agg2l);
    cudaGetSymbolAddress((void**)&combh, g_combh);
    cudaGetSymbolAddress((void**)&combl, g_combl);
    cudaGetSymbolAddress((void**)&wth, g_wth);
    cudaGetSymbolAddress((void**)&wtl, g_wtl);

    // BM=64 layer kernels: A 2x16KB + B 2x32KB = 96KB -> occupancy 2
    const int SM_L = 2 * (64 * 128 * 2) + 2 * (128 * 128 * 2);    // 98304
    const int SM64 = 2 * (128 * 256 * 2) + 2 * (64 * 256 * 2);    // 196608
    static bool attr_done = false;
    if (!attr_done) {
        cudaFuncSetAttribute(k_mma<64, 128, 128>, cudaFuncAttributeMaxDynamicSharedMemorySize, SM_L);
        cudaFuncSetAttribute(k_mma<128, 64, 256>, cudaFuncAttributeMaxDynamicSharedMemorySize, SM64);
        attr_done = true;
    }

    const int TB = 256;
    k_detect_init<<<(N_NODES + TB - 1) / TB, TB>>>(ei32);
    k_extract_count<<<(N_EDGES + TB - 1) / TB, TB>>>(ei32);
    k_scan_dinv<<<1, 1024>>>();
    k_fill<<<(N_EDGES + TB - 1) / TB, TB>>>();

    {
        PrepB p;
        p.W[0] = W_s1;  p.K[0] = 128; p.N[0] = 128;
        p.W[1] = W_m21; p.K[1] = 128; p.N[1] = 128;
        p.W[2] = W_m1;  p.K[2] = 128; p.N[2] = 128;
        p.W[3] = W_s2;  p.K[3] = 128; p.N[3] = 128;
        p.W[4] = W_m22; p.K[4] = 128; p.N[4] = 128;
        p.W[5] = W_fc;  p.K[5] = 256; p.N[5] = 64;
        k_prepB<<<6, 256>>>(p);
    }

    k_agg128<<<N_NODES / 8, 256>>>(x, aggxh, aggxl);

    const int MT64 = (N_NODES + 63) / 64;   // 782

    {
        MJobs j = {};
        for (int q = 0; q < 3; q++) { j.Ah[q] = aggxh; j.Al[q] = aggxl; j.lda[q] = 128; j.split[q] = 0; }
        j.Bh[0] = wth + 0 * 16384; j.Bl[0] = wtl + 0 * 16384; j.bias[0] = b_s1;  j.C[0] = bufA;       j.ldc[0] = 256;
        j.Bh[1] = wth + 1 * 16384; j.Bl[1] = wtl + 1 * 16384; j.bias[1] = b_m21; j.C[1] = bufA + 128; j.ldc[1] = 256;
        j.Bh[2] = wth + 2 * 16384; j.Bl[2] = wtl + 2 * 16384; j.bias[2] = b_m1;  j.C[2] = h1;         j.ldc[2] = 128;
        k_mma<64, 128, 128><<<dim3(1, MT64, 3), 256, SM_L>>>(j, 1);
    }

    k_agg256<<<N_NODES / 8, 256>>>(bufA, agg2h, agg2l);

    {
        MJobs j = {};
        j.Ah[0] = agg2h;       j.Al[0] = agg2l;       j.lda[0] = 256;
        j.Ah[1] = agg2h + 128; j.Al[1] = agg2l + 128; j.lda[1] = 256;
        j.Ah[2] = j.Ah[0];     j.Al[2] = j.Al[0];     j.lda[2] = 256;
        j.Bh[0] = wth + 3 * 16384; j.Bl[0] = wtl + 3 * 16384; j.bias[0] = b_s2;
        j.Cbh[0] = combh; j.Cbl[0] = combl; j.ldc[0] = 256; j.split[0] = 1;
        j.Bh[1] = wth + 4 * 16384; j.Bl[1] = wtl + 4 * 16384; j.bias[1] = b_m22;
        j.C[1] = h2; j.ldc[1] = 128; j.split[1] = 0;
        j.Bh[2] = j.Bh[0]; j.Bl[2] = j.Bl[0]; j.bias[2] = j.bias[0];
        j.Cbh[2] = j.Cbh[0]; j.Cbl[2] = j.Cbl[0]; j.ldc[2] = j.ldc[0]; j.split[2] = 1;
        k_mma<64, 128, 128><<<dim3(1, MT64, 2), 256, SM_L>>>(j, 1);
    }

    k_attn<<<N_NODES / 2, 256>>>(W_att, b_att);

    {
        MJobs j = {};
        for (int q = 0; q < 3; q++) {
            j.Ah[q] = combh; j.Al[q] = combl; j.lda[q] = 256;
            j.Bh[q] = wth + 5 * 16384; j.Bl[q] = wtl + 5 * 16384;
            j.bias[q] = b_fc; j.C[q] = out; j.ldc[q] = 64; j.split[q] = 0;
        }
        k_mma<128, 64, 256><<<dim3(1, (N_NODES + 127) / 128, 1), 256, SM64>>>(j, 0);
    }

    (void)in_sizes; (void)n_in; (void)out_size;
}